// round 14
// baseline (speedup 1.0000x reference)
#include <cuda_runtime.h>
#include <cuda_fp16.h>
#include <math.h>
#include <stdint.h>

#define N_NODES 50000
#define N_EDGES 800000
#define D_IN    256
#define D_HID   128
#define D_ENC   64
#define MAXDEG  96
#define GEMM_BLOCKS ((N_NODES + 127) / 128)          // 391

// ---------------- scratch (static device globals; no allocations) ----------
__device__ int            d_counts[N_NODES];
__device__ float          d_dinv[N_NODES];
__device__ __half         d_dinvh[N_NODES];               // fp16 copy of dinv
__device__ unsigned short d_ell[(size_t)N_NODES * MAXDEG]; // adjacency (u16 ids)
__device__ __half         d_g[(size_t)N_NODES * D_HID];    // x @ W1 (unscaled fp16)
__device__ float          d_td[N_NODES];                   // dinv[i] * (h1 . v)
__device__ float          d_v[D_HID];                      // W2 @ Wfc
__device__ float          d_s;                             // b2 . Wfc + bfc
__device__ float          d_W1t[D_HID * D_IN];             // W1 transposed [n][k]

__device__ __forceinline__ int clamp_node(int v) {
    return (v >= 0 && v < N_NODES) ? v : 0;
}

__device__ __forceinline__ uint32_t pack_bf16(float lo, float hi) {
    uint32_t r;
    asm("cvt.rn.bf16x2.f32 %0, %1, %2;" : "=r"(r) : "f"(hi), "f"(lo));
    return r;
}

// ---------------- single-pass ELL build (count + place) ---------------------
__global__ void fill_ell_kernel(const int* __restrict__ row,
                                const int* __restrict__ col) {
    int e = (blockIdx.x * blockDim.x + threadIdx.x) * 4;
    if (e + 3 < N_EDGES) {
        int4 c = *reinterpret_cast<const int4*>(col + e);
        int4 r = *reinterpret_cast<const int4*>(row + e);
        int c0 = clamp_node(c.x), c1 = clamp_node(c.y);
        int c2 = clamp_node(c.z), c3 = clamp_node(c.w);
        int p0 = atomicAdd(&d_counts[c0], 1);
        int p1 = atomicAdd(&d_counts[c1], 1);
        int p2 = atomicAdd(&d_counts[c2], 1);
        int p3 = atomicAdd(&d_counts[c3], 1);
        if (p0 < MAXDEG) d_ell[(size_t)c0 * MAXDEG + p0] = (unsigned short)clamp_node(r.x);
        if (p1 < MAXDEG) d_ell[(size_t)c1 * MAXDEG + p1] = (unsigned short)clamp_node(r.y);
        if (p2 < MAXDEG) d_ell[(size_t)c2 * MAXDEG + p2] = (unsigned short)clamp_node(r.z);
        if (p3 < MAXDEG) d_ell[(size_t)c3 * MAXDEG + p3] = (unsigned short)clamp_node(r.w);
    } else {
        for (int k = e; k < N_EDGES; k++) {
            int cc = clamp_node(col[k]);
            int p = atomicAdd(&d_counts[cc], 1);
            if (p < MAXDEG) d_ell[(size_t)cc * MAXDEG + p] = (unsigned short)clamp_node(row[k]);
        }
    }
}

// ---------------- weight prep: transpose W1 (32 blocks) + v,s (1 block) -----
__global__ void prep_weights_kernel(const float* __restrict__ W1,
                                    const float* __restrict__ W2,
                                    const float* __restrict__ b2,
                                    const float* __restrict__ Wfc,
                                    const float* __restrict__ bfc) {
    if (blockIdx.x < 32) {
        __shared__ float tt[32][33];
        int b = blockIdx.x;
        int bx = b & 7;
        int by = b >> 3;
        int x0 = bx * 32, y0 = by * 32;
        int tx = threadIdx.x & 31, ty = threadIdx.x >> 5;
        #pragma unroll
        for (int i = 0; i < 32; i += 8)
            tt[ty + i][tx] = W1[(size_t)(x0 + ty + i) * D_HID + y0 + tx];
        __syncthreads();
        #pragma unroll
        for (int i = 0; i < 32; i += 8)
            d_W1t[(size_t)(y0 + ty + i) * D_IN + x0 + tx] = tt[tx][ty + i];
    } else {
        __shared__ float red[D_ENC];
        int j = threadIdx.x;
        if (j < D_HID) {
            float acc = 0.f;
            #pragma unroll 8
            for (int k = 0; k < D_ENC; k++)
                acc = fmaf(W2[j * D_ENC + k], Wfc[k], acc);
            d_v[j] = acc;
        }
        if (j < D_ENC) red[j] = b2[j] * Wfc[j];
        __syncthreads();
        if (j == 0) {
            float s = bfc[0];
            for (int k = 0; k < D_ENC; k++) s += red[k];
            d_s = s;
        }
    }
}

// ---------------- GEMM1 (bf16 m16n8k16 mma); UNSCALED fp16 output -----------
__global__ __launch_bounds__(256) void gemm1_mma_kernel(const float* __restrict__ x) {
    __shared__ uint32_t As[128][20];
    __shared__ uint32_t Bs[128][20];

    int tid  = threadIdx.x;
    int warp = tid >> 5;
    int lane = tid & 31;
    int g  = lane >> 2;
    int tg = lane & 3;
    int rowBase = blockIdx.x * 128;

    float acc[16][4];
    #pragma unroll
    for (int nt = 0; nt < 16; nt++)
        #pragma unroll
        for (int i = 0; i < 4; i++) acc[nt][i] = 0.f;

    int lr = tid >> 1;
    int h  = tid & 1;
    int gr = rowBase + lr;
    bool valid = gr < N_NODES;
    const float4* pA = reinterpret_cast<const float4*>(
        x + (size_t)(valid ? gr : 0) * D_IN + h * 16);
    const float4* pB = reinterpret_cast<const float4*>(
        d_W1t + (size_t)lr * D_IN + h * 16);

    float4 ra[4], rb[4];
    #pragma unroll
    for (int i = 0; i < 4; i++) {
        ra[i] = valid ? pA[i] : make_float4(0.f, 0.f, 0.f, 0.f);
        rb[i] = pB[i];
    }
    #pragma unroll
    for (int i = 0; i < 4; i++) {
        As[lr][h * 8 + i * 2    ] = pack_bf16(ra[i].x, ra[i].y);
        As[lr][h * 8 + i * 2 + 1] = pack_bf16(ra[i].z, ra[i].w);
        Bs[lr][h * 8 + i * 2    ] = pack_bf16(rb[i].x, rb[i].y);
        Bs[lr][h * 8 + i * 2 + 1] = pack_bf16(rb[i].z, rb[i].w);
    }
    __syncthreads();

    #pragma unroll
    for (int c = 0; c < 8; c++) {
        if (c < 7) {
            #pragma unroll
            for (int i = 0; i < 4; i++) {
                ra[i] = valid ? pA[(c + 1) * 8 + i] : make_float4(0.f, 0.f, 0.f, 0.f);
                rb[i] = pB[(c + 1) * 8 + i];
            }
        }
        #pragma unroll
        for (int kk = 0; kk < 2; kk++) {
            uint32_t a0 = As[warp * 16 + g    ][kk * 8 + tg    ];
            uint32_t a1 = As[warp * 16 + g + 8][kk * 8 + tg    ];
            uint32_t a2 = As[warp * 16 + g    ][kk * 8 + 4 + tg];
            uint32_t a3 = As[warp * 16 + g + 8][kk * 8 + 4 + tg];
            #pragma unroll
            for (int nt = 0; nt < 16; nt++) {
                uint32_t b0 = Bs[nt * 8 + g][kk * 8 + tg    ];
                uint32_t b1 = Bs[nt * 8 + g][kk * 8 + 4 + tg];
                asm volatile(
                    "mma.sync.aligned.m16n8k16.row.col.f32.bf16.bf16.f32 "
                    "{%0,%1,%2,%3}, {%4,%5,%6,%7}, {%8,%9}, {%0,%1,%2,%3};"
                    : "+f"(acc[nt][0]), "+f"(acc[nt][1]),
                      "+f"(acc[nt][2]), "+f"(acc[nt][3])
                    : "r"(a0), "r"(a1), "r"(a2), "r"(a3), "r"(b0), "r"(b1));
            }
        }
        if (c < 7) {
            __syncthreads();
            #pragma unroll
            for (int i = 0; i < 4; i++) {
                As[lr][h * 8 + i * 2    ] = pack_bf16(ra[i].x, ra[i].y);
                As[lr][h * 8 + i * 2 + 1] = pack_bf16(ra[i].z, ra[i].w);
                Bs[lr][h * 8 + i * 2    ] = pack_bf16(rb[i].x, rb[i].y);
                Bs[lr][h * 8 + i * 2 + 1] = pack_bf16(rb[i].z, rb[i].w);
            }
            __syncthreads();
        }
    }

    int r0 = rowBase + warp * 16 + g;
    int r1 = r0 + 8;
    __half2* g2 = reinterpret_cast<__half2*>(d_g);
    #pragma unroll
    for (int nt = 0; nt < 16; nt++) {
        int hh = nt * 4 + tg;
        if (r0 < N_NODES)
            g2[(size_t)r0 * 64 + hh] = __floats2half2_rn(acc[nt][0], acc[nt][1]);
        if (r1 < N_NODES)
            g2[(size_t)r1 * 64 + hh] = __floats2half2_rn(acc[nt][2], acc[nt][3]);
    }
}

// ---------------- dinv pack: counts -> dinv (f32 + f16) ----------------------
__global__ void dinv_pack_kernel() {
    int i = blockIdx.x * blockDim.x + threadIdx.x;
    if (i >= N_NODES) return;
    float di = rsqrtf((float)(d_counts[i] + 1));   // deg = cnt + 1
    d_dinv[i]  = di;
    d_dinvh[i] = __float2half(di);
}

// ---------------- layer-1 aggregation: fp16-weighted sum --------------------
__global__ __launch_bounds__(256) void agg1_kernel(const float* __restrict__ b1) {
    int gwarp = (blockIdx.x * blockDim.x + threadIdx.x) >> 5;
    int lane  = threadIdx.x & 31;
    if (gwarp >= N_NODES) return;
    int node  = gwarp;
    int cnt   = d_counts[node];
    if (cnt > MAXDEG) cnt = MAXDEG;
    const unsigned short* adj = d_ell + (size_t)node * MAXDEG;
    float di  = d_dinv[node];
    const uint2* g4 = reinterpret_cast<const uint2*>(d_g);

    float4 acc = make_float4(0.f, 0.f, 0.f, 0.f);
    int j = 0;
    for (; j + 4 <= cnt; j += 4) {
        ushort4 ss = *reinterpret_cast<const ushort4*>(adj + j);
        __half2 w0 = __half2half2(d_dinvh[ss.x]);   // broadcast gathers
        __half2 w1 = __half2half2(d_dinvh[ss.y]);
        __half2 w2 = __half2half2(d_dinvh[ss.z]);
        __half2 w3 = __half2half2(d_dinvh[ss.w]);
        uint2 u0 = g4[(size_t)ss.x * 32 + lane];
        uint2 u1 = g4[(size_t)ss.y * 32 + lane];
        uint2 u2 = g4[(size_t)ss.z * 32 + lane];
        uint2 u3 = g4[(size_t)ss.w * 32 + lane];
        // depth-1 weighted fp16 pair sums, then fp32 accumulate
        __half2 h01a = __hfma2(*reinterpret_cast<__half2*>(&u1.x), w1,
                       __hmul2(*reinterpret_cast<__half2*>(&u0.x), w0));
        __half2 h01b = __hfma2(*reinterpret_cast<__half2*>(&u1.y), w1,
                       __hmul2(*reinterpret_cast<__half2*>(&u0.y), w0));
        __half2 h23a = __hfma2(*reinterpret_cast<__half2*>(&u3.x), w3,
                       __hmul2(*reinterpret_cast<__half2*>(&u2.x), w2));
        __half2 h23b = __hfma2(*reinterpret_cast<__half2*>(&u3.y), w3,
                       __hmul2(*reinterpret_cast<__half2*>(&u2.y), w2));
        float2 f0 = __half22float2(h01a);
        float2 f1 = __half22float2(h01b);
        float2 f2 = __half22float2(h23a);
        float2 f3 = __half22float2(h23b);
        acc.x += f0.x + f2.x; acc.y += f0.y + f2.y;
        acc.z += f1.x + f3.x; acc.w += f1.y + f3.y;
    }
    for (; j < cnt; j++) {
        int s0 = adj[j];
        float wf = d_dinv[s0];
        uint2 u0 = g4[(size_t)s0 * 32 + lane];
        float2 a0 = __half22float2(*reinterpret_cast<__half2*>(&u0.x));
        float2 a1 = __half22float2(*reinterpret_cast<__half2*>(&u0.y));
        acc.x += wf * a0.x; acc.y += wf * a0.y;
        acc.z += wf * a1.x; acc.w += wf * a1.y;
    }
    {   // self loop: weight = dinv[node] (fp32)
        uint2 u0 = g4[(size_t)node * 32 + lane];
        float2 a0 = __half22float2(*reinterpret_cast<__half2*>(&u0.x));
        float2 a1 = __half22float2(*reinterpret_cast<__half2*>(&u0.y));
        acc.x += di * a0.x; acc.y += di * a0.y;
        acc.z += di * a1.x; acc.w += di * a1.y;
    }
    float4 bb = reinterpret_cast<const float4*>(b1)[lane];
    float4 vv = reinterpret_cast<const float4*>(d_v)[lane];
    float h0 = fmaxf(fmaf(acc.x, di, bb.x), 0.f);
    float h1 = fmaxf(fmaf(acc.y, di, bb.y), 0.f);
    float h2 = fmaxf(fmaf(acc.z, di, bb.z), 0.f);
    float h3 = fmaxf(fmaf(acc.w, di, bb.w), 0.f);
    float p = h0 * vv.x + h1 * vv.y + h2 * vv.z + h3 * vv.w;
    #pragma unroll
    for (int off = 16; off > 0; off >>= 1)
        p += __shfl_down_sync(0xFFFFFFFFu, p, off);
    if (lane == 0) d_td[node] = di * p;
}

// ---------------- layer-2 (collapsed, scalar) + sigmoid ---------------------
__global__ void agg2_kernel(float* __restrict__ out) {
    int i = blockIdx.x * blockDim.x + threadIdx.x;
    if (i >= N_NODES) return;
    int cnt = d_counts[i];
    if (cnt > MAXDEG) cnt = MAXDEG;
    const unsigned short* adj = d_ell + (size_t)i * MAXDEG;
    float acc = 0.f;
    int j = 0;
    for (; j + 4 <= cnt; j += 4) {
        ushort4 ss = *reinterpret_cast<const ushort4*>(adj + j);
        acc += d_td[ss.x] + d_td[ss.y] + d_td[ss.z] + d_td[ss.w];
    }
    for (; j < cnt; j++) acc += d_td[adj[j]];
    float di = d_dinv[i];
    float u = di * (acc + d_td[i]) + d_s;
    out[i] = 1.f / (1.f + expf(-u));
}

// ---------------- launcher with fork/join overlap ---------------------------
extern "C" void kernel_launch(void* const* d_in, const int* in_sizes, int n_in,
                              void* d_out, int out_size) {
    const float* x   = (const float*)d_in[0];
    const int*   ei  = (const int*)d_in[1];
    const float* W1  = (const float*)d_in[2];
    const float* b1  = (const float*)d_in[3];
    const float* W2  = (const float*)d_in[4];
    const float* b2  = (const float*)d_in[5];
    const float* Wfc = (const float*)d_in[6];
    const float* bfc = (const float*)d_in[7];
    float* out = (float*)d_out;

    const int* row = ei;            // sources
    const int* col = ei + N_EDGES;  // targets

    static cudaStream_t side = nullptr;
    static cudaEvent_t  evFork = nullptr, evJoin = nullptr;
    if (side == nullptr) {
        cudaStreamCreateWithFlags(&side, cudaStreamNonBlocking);
        cudaEventCreateWithFlags(&evFork, cudaEventDisableTiming);
        cudaEventCreateWithFlags(&evJoin, cudaEventDisableTiming);
    }

    void* counts_ptr = nullptr;
    cudaGetSymbolAddress(&counts_ptr, d_counts);

    // fork: side stream does weight prep + GEMM (independent of edges)
    cudaEventRecord(evFork, 0);
    cudaStreamWaitEvent(side, evFork, 0);
    prep_weights_kernel<<<33, 256, 0, side>>>(W1, W2, b2, Wfc, bfc);
    gemm1_mma_kernel<<<GEMM_BLOCKS, 256, 0, side>>>(x);

    // main stream: counts reset + ELL build + dinv pack
    cudaMemsetAsync(counts_ptr, 0, N_NODES * sizeof(int), 0);
    fill_ell_kernel<<<(N_EDGES / 4 + 255) / 256, 256, 0, 0>>>(row, col);
    dinv_pack_kernel<<<(N_NODES + 255) / 256, 256, 0, 0>>>();

    // join
    cudaEventRecord(evJoin, side);
    cudaStreamWaitEvent(0, evJoin, 0);

    agg1_kernel<<<(N_NODES + 7) / 8, 256, 0, 0>>>(b1);
    agg2_kernel<<<(N_NODES + 255) / 256, 256, 0, 0>>>(out);
}

// round 15
// speedup vs baseline: 1.0203x; 1.0203x over previous
#include <cuda_runtime.h>
#include <cuda_fp16.h>
#include <math.h>
#include <stdint.h>

#define N_NODES 50000
#define N_EDGES 800000
#define D_IN    256
#define D_HID   128
#define D_ENC   64
#define MAXDEG  96
#define GEMM_BLOCKS ((N_NODES + 127) / 128)          // 391

// ---------------- scratch (static device globals; no allocations) ----------
__device__ int            d_counts[N_NODES];
__device__ float          d_dinv[N_NODES];
__device__ unsigned short d_ell[(size_t)N_NODES * MAXDEG]; // adjacency (u16 ids)
__device__ __half         d_g[(size_t)N_NODES * D_HID];    // (x@W1), then scaled
__device__ float          d_td[N_NODES];                   // dinv[i] * (h1 . v)
__device__ float          d_v[D_HID];                      // W2 @ Wfc
__device__ float          d_s;                             // b2 . Wfc + bfc
__device__ float          d_W1t[D_HID * D_IN];             // W1 transposed [n][k]

__device__ __forceinline__ int clamp_node(int v) {
    return (v >= 0 && v < N_NODES) ? v : 0;
}

__device__ __forceinline__ uint32_t pack_bf16(float lo, float hi) {
    uint32_t r;
    asm("cvt.rn.bf16x2.f32 %0, %1, %2;" : "=r"(r) : "f"(hi), "f"(lo));
    return r;
}

// ---------------- single-pass ELL build (count + place) ---------------------
__global__ void fill_ell_kernel(const int* __restrict__ row,
                                const int* __restrict__ col) {
    int e = (blockIdx.x * blockDim.x + threadIdx.x) * 4;
    if (e + 3 < N_EDGES) {
        int4 c = *reinterpret_cast<const int4*>(col + e);
        int4 r = *reinterpret_cast<const int4*>(row + e);
        int c0 = clamp_node(c.x), c1 = clamp_node(c.y);
        int c2 = clamp_node(c.z), c3 = clamp_node(c.w);
        int p0 = atomicAdd(&d_counts[c0], 1);
        int p1 = atomicAdd(&d_counts[c1], 1);
        int p2 = atomicAdd(&d_counts[c2], 1);
        int p3 = atomicAdd(&d_counts[c3], 1);
        if (p0 < MAXDEG) d_ell[(size_t)c0 * MAXDEG + p0] = (unsigned short)clamp_node(r.x);
        if (p1 < MAXDEG) d_ell[(size_t)c1 * MAXDEG + p1] = (unsigned short)clamp_node(r.y);
        if (p2 < MAXDEG) d_ell[(size_t)c2 * MAXDEG + p2] = (unsigned short)clamp_node(r.z);
        if (p3 < MAXDEG) d_ell[(size_t)c3 * MAXDEG + p3] = (unsigned short)clamp_node(r.w);
    } else {
        for (int k = e; k < N_EDGES; k++) {
            int cc = clamp_node(col[k]);
            int p = atomicAdd(&d_counts[cc], 1);
            if (p < MAXDEG) d_ell[(size_t)cc * MAXDEG + p] = (unsigned short)clamp_node(row[k]);
        }
    }
}

// ---------------- weight prep: transpose W1 (32 blocks) + v,s (1 block) -----
__global__ void prep_weights_kernel(const float* __restrict__ W1,
                                    const float* __restrict__ W2,
                                    const float* __restrict__ b2,
                                    const float* __restrict__ Wfc,
                                    const float* __restrict__ bfc) {
    if (blockIdx.x < 32) {
        __shared__ float tt[32][33];
        int b = blockIdx.x;
        int bx = b & 7;
        int by = b >> 3;
        int x0 = bx * 32, y0 = by * 32;
        int tx = threadIdx.x & 31, ty = threadIdx.x >> 5;
        #pragma unroll
        for (int i = 0; i < 32; i += 8)
            tt[ty + i][tx] = W1[(size_t)(x0 + ty + i) * D_HID + y0 + tx];
        __syncthreads();
        #pragma unroll
        for (int i = 0; i < 32; i += 8)
            d_W1t[(size_t)(y0 + ty + i) * D_IN + x0 + tx] = tt[tx][ty + i];
    } else {
        __shared__ float red[D_ENC];
        int j = threadIdx.x;
        if (j < D_HID) {
            float acc = 0.f;
            #pragma unroll 8
            for (int k = 0; k < D_ENC; k++)
                acc = fmaf(W2[j * D_ENC + k], Wfc[k], acc);
            d_v[j] = acc;
        }
        if (j < D_ENC) red[j] = b2[j] * Wfc[j];
        __syncthreads();
        if (j == 0) {
            float s = bfc[0];
            for (int k = 0; k < D_ENC; k++) s += red[k];
            d_s = s;
        }
    }
}

// ---------------- GEMM1 (bf16 m16n8k16, permuted smem, LDS.64 fragments) ----
// physical col within each 8-word group: l -> (l<4) ? 2l : 2(l-4)+1
// so fragment pairs (tg, tg+4) are adjacent -> one LDS.64 each.
__global__ __launch_bounds__(256) void gemm1_mma_kernel(const float* __restrict__ x) {
    __shared__ uint32_t As[128][24];   // stride 24: conflict-free LDS.64 phases
    __shared__ uint32_t Bs[128][24];

    int tid  = threadIdx.x;
    int warp = tid >> 5;
    int lane = tid & 31;
    int g  = lane >> 2;
    int tg = lane & 3;
    int rowBase = blockIdx.x * 128;

    float acc[16][4];
    #pragma unroll
    for (int nt = 0; nt < 16; nt++)
        #pragma unroll
        for (int i = 0; i < 4; i++) acc[nt][i] = 0.f;

    int lr = tid >> 1;
    int h  = tid & 1;
    int gr = rowBase + lr;
    bool valid = gr < N_NODES;
    const float4* pA = reinterpret_cast<const float4*>(
        x + (size_t)(valid ? gr : 0) * D_IN + h * 16);
    const float4* pB = reinterpret_cast<const float4*>(
        d_W1t + (size_t)lr * D_IN + h * 16);

    float4 ra[4], rb[4];
    #pragma unroll
    for (int i = 0; i < 4; i++) {
        ra[i] = valid ? pA[i] : make_float4(0.f, 0.f, 0.f, 0.f);
        rb[i] = pB[i];
    }
    // permuted store: phys pairs {(l0,l4),(l1,l5),(l2,l6),(l3,l7)} as uint2
    {
        uint2* As2 = reinterpret_cast<uint2*>(&As[lr][h * 8]);
        uint2* Bs2 = reinterpret_cast<uint2*>(&Bs[lr][h * 8]);
        As2[0] = make_uint2(pack_bf16(ra[0].x, ra[0].y), pack_bf16(ra[2].x, ra[2].y));
        As2[1] = make_uint2(pack_bf16(ra[0].z, ra[0].w), pack_bf16(ra[2].z, ra[2].w));
        As2[2] = make_uint2(pack_bf16(ra[1].x, ra[1].y), pack_bf16(ra[3].x, ra[3].y));
        As2[3] = make_uint2(pack_bf16(ra[1].z, ra[1].w), pack_bf16(ra[3].z, ra[3].w));
        Bs2[0] = make_uint2(pack_bf16(rb[0].x, rb[0].y), pack_bf16(rb[2].x, rb[2].y));
        Bs2[1] = make_uint2(pack_bf16(rb[0].z, rb[0].w), pack_bf16(rb[2].z, rb[2].w));
        Bs2[2] = make_uint2(pack_bf16(rb[1].x, rb[1].y), pack_bf16(rb[3].x, rb[3].y));
        Bs2[3] = make_uint2(pack_bf16(rb[1].z, rb[1].w), pack_bf16(rb[3].z, rb[3].w));
    }
    __syncthreads();

    #pragma unroll
    for (int c = 0; c < 8; c++) {
        if (c < 7) {
            #pragma unroll
            for (int i = 0; i < 4; i++) {
                ra[i] = valid ? pA[(c + 1) * 8 + i] : make_float4(0.f, 0.f, 0.f, 0.f);
                rb[i] = pB[(c + 1) * 8 + i];
            }
        }
        #pragma unroll
        for (int kk = 0; kk < 2; kk++) {
            uint2 aA = *reinterpret_cast<const uint2*>(
                &As[warp * 16 + g    ][kk * 8 + 2 * tg]);   // {a0, a2}
            uint2 aB = *reinterpret_cast<const uint2*>(
                &As[warp * 16 + g + 8][kk * 8 + 2 * tg]);   // {a1, a3}
            #pragma unroll
            for (int nt = 0; nt < 16; nt++) {
                uint2 bb = *reinterpret_cast<const uint2*>(
                    &Bs[nt * 8 + g][kk * 8 + 2 * tg]);      // {b0, b1}
                asm volatile(
                    "mma.sync.aligned.m16n8k16.row.col.f32.bf16.bf16.f32 "
                    "{%0,%1,%2,%3}, {%4,%5,%6,%7}, {%8,%9}, {%0,%1,%2,%3};"
                    : "+f"(acc[nt][0]), "+f"(acc[nt][1]),
                      "+f"(acc[nt][2]), "+f"(acc[nt][3])
                    : "r"(aA.x), "r"(aB.x), "r"(aA.y), "r"(aB.y),
                      "r"(bb.x), "r"(bb.y));
            }
        }
        if (c < 7) {
            __syncthreads();
            uint2* As2 = reinterpret_cast<uint2*>(&As[lr][h * 8]);
            uint2* Bs2 = reinterpret_cast<uint2*>(&Bs[lr][h * 8]);
            As2[0] = make_uint2(pack_bf16(ra[0].x, ra[0].y), pack_bf16(ra[2].x, ra[2].y));
            As2[1] = make_uint2(pack_bf16(ra[0].z, ra[0].w), pack_bf16(ra[2].z, ra[2].w));
            As2[2] = make_uint2(pack_bf16(ra[1].x, ra[1].y), pack_bf16(ra[3].x, ra[3].y));
            As2[3] = make_uint2(pack_bf16(ra[1].z, ra[1].w), pack_bf16(ra[3].z, ra[3].w));
            Bs2[0] = make_uint2(pack_bf16(rb[0].x, rb[0].y), pack_bf16(rb[2].x, rb[2].y));
            Bs2[1] = make_uint2(pack_bf16(rb[0].z, rb[0].w), pack_bf16(rb[2].z, rb[2].w));
            Bs2[2] = make_uint2(pack_bf16(rb[1].x, rb[1].y), pack_bf16(rb[3].x, rb[3].y));
            Bs2[3] = make_uint2(pack_bf16(rb[1].z, rb[1].w), pack_bf16(rb[3].z, rb[3].w));
            __syncthreads();
        }
    }

    int r0 = rowBase + warp * 16 + g;
    int r1 = r0 + 8;
    __half2* g2 = reinterpret_cast<__half2*>(d_g);
    #pragma unroll
    for (int nt = 0; nt < 16; nt++) {
        int hh = nt * 4 + tg;
        if (r0 < N_NODES)
            g2[(size_t)r0 * 64 + hh] = __floats2half2_rn(acc[nt][0], acc[nt][1]);
        if (r1 < N_NODES)
            g2[(size_t)r1 * 64 + hh] = __floats2half2_rn(acc[nt][2], acc[nt][3]);
    }
}

// ---------------- scale g rows by dinv (MLP=2); emit d_dinv -----------------
#define SCALE_HALF (N_NODES * 8)   // 400000 uint4s per half
__global__ __launch_bounds__(256) void scale_g_kernel() {
    int t = blockIdx.x * blockDim.x + threadIdx.x;
    if (t >= SCALE_HALF) return;
    int idx0 = t;
    int idx1 = t + SCALE_HALF;
    uint4* g16 = reinterpret_cast<uint4*>(d_g);
    int row0 = idx0 >> 4;
    int row1 = idx1 >> 4;
    int c0 = d_counts[row0];
    int c1 = d_counts[row1];
    uint4 u0 = g16[idx0];
    uint4 u1 = g16[idx1];
    float di0 = rsqrtf((float)(c0 + 1));
    float di1 = rsqrtf((float)(c1 + 1));
    if ((idx0 & 15) == 0) d_dinv[row0] = di0;
    if ((idx1 & 15) == 0) d_dinv[row1] = di1;
    __half2* h0 = reinterpret_cast<__half2*>(&u0);
    __half2* h1 = reinterpret_cast<__half2*>(&u1);
    #pragma unroll
    for (int i = 0; i < 4; i++) {
        float2 f0 = __half22float2(h0[i]);
        float2 f1 = __half22float2(h1[i]);
        h0[i] = __floats2half2_rn(di0 * f0.x, di0 * f0.y);
        h1[i] = __floats2half2_rn(di1 * f1.x, di1 * f1.y);
    }
    g16[idx0] = u0;
    g16[idx1] = u1;
}

// ---------------- layer-1 aggregation: u16 indices + depth-1 HADD2 ----------
__global__ __launch_bounds__(256) void agg1_kernel(const float* __restrict__ b1) {
    int gwarp = (blockIdx.x * blockDim.x + threadIdx.x) >> 5;
    int lane  = threadIdx.x & 31;
    if (gwarp >= N_NODES) return;
    int node  = gwarp;
    int cnt   = d_counts[node];
    if (cnt > MAXDEG) cnt = MAXDEG;
    const unsigned short* adj = d_ell + (size_t)node * MAXDEG;
    float di  = d_dinv[node];
    const uint2* g4 = reinterpret_cast<const uint2*>(d_g);

    float4 acc = make_float4(0.f, 0.f, 0.f, 0.f);
    int j = 0;
    for (; j + 4 <= cnt; j += 4) {
        ushort4 ss = *reinterpret_cast<const ushort4*>(adj + j);
        uint2 u0 = g4[(size_t)ss.x * 32 + lane];
        uint2 u1 = g4[(size_t)ss.y * 32 + lane];
        uint2 u2 = g4[(size_t)ss.z * 32 + lane];
        uint2 u3 = g4[(size_t)ss.w * 32 + lane];
        __half2 h01a = __hadd2(*reinterpret_cast<__half2*>(&u0.x),
                               *reinterpret_cast<__half2*>(&u1.x));
        __half2 h01b = __hadd2(*reinterpret_cast<__half2*>(&u0.y),
                               *reinterpret_cast<__half2*>(&u1.y));
        __half2 h23a = __hadd2(*reinterpret_cast<__half2*>(&u2.x),
                               *reinterpret_cast<__half2*>(&u3.x));
        __half2 h23b = __hadd2(*reinterpret_cast<__half2*>(&u2.y),
                               *reinterpret_cast<__half2*>(&u3.y));
        float2 f0 = __half22float2(h01a);
        float2 f1 = __half22float2(h01b);
        float2 f2 = __half22float2(h23a);
        float2 f3 = __half22float2(h23b);
        acc.x += f0.x + f2.x; acc.y += f0.y + f2.y;
        acc.z += f1.x + f3.x; acc.w += f1.y + f3.y;
    }
    for (; j < cnt; j++) {
        int s0 = adj[j];
        uint2 u0 = g4[(size_t)s0 * 32 + lane];
        float2 a0 = __half22float2(*reinterpret_cast<__half2*>(&u0.x));
        float2 a1 = __half22float2(*reinterpret_cast<__half2*>(&u0.y));
        acc.x += a0.x; acc.y += a0.y;
        acc.z += a1.x; acc.w += a1.y;
    }
    {   // self loop (row pre-scaled by dinv[node])
        uint2 u0 = g4[(size_t)node * 32 + lane];
        float2 a0 = __half22float2(*reinterpret_cast<__half2*>(&u0.x));
        float2 a1 = __half22float2(*reinterpret_cast<__half2*>(&u0.y));
        acc.x += a0.x; acc.y += a0.y;
        acc.z += a1.x; acc.w += a1.y;
    }
    float4 bb = reinterpret_cast<const float4*>(b1)[lane];
    float4 vv = reinterpret_cast<const float4*>(d_v)[lane];
    float h0 = fmaxf(fmaf(acc.x, di, bb.x), 0.f);
    float h1 = fmaxf(fmaf(acc.y, di, bb.y), 0.f);
    float h2 = fmaxf(fmaf(acc.z, di, bb.z), 0.f);
    float h3 = fmaxf(fmaf(acc.w, di, bb.w), 0.f);
    float p = h0 * vv.x + h1 * vv.y + h2 * vv.z + h3 * vv.w;
    #pragma unroll
    for (int off = 16; off > 0; off >>= 1)
        p += __shfl_down_sync(0xFFFFFFFFu, p, off);
    if (lane == 0) d_td[node] = di * p;
}

// ---------------- layer-2 (collapsed, scalar) + sigmoid ---------------------
__global__ void agg2_kernel(float* __restrict__ out) {
    int i = blockIdx.x * blockDim.x + threadIdx.x;
    if (i >= N_NODES) return;
    int cnt = d_counts[i];
    if (cnt > MAXDEG) cnt = MAXDEG;
    const unsigned short* adj = d_ell + (size_t)i * MAXDEG;
    float acc = 0.f;
    int j = 0;
    for (; j + 4 <= cnt; j += 4) {
        ushort4 ss = *reinterpret_cast<const ushort4*>(adj + j);
        acc += d_td[ss.x] + d_td[ss.y] + d_td[ss.z] + d_td[ss.w];
    }
    for (; j < cnt; j++) acc += d_td[adj[j]];
    float di = d_dinv[i];
    float u = di * (acc + d_td[i]) + d_s;
    out[i] = 1.f / (1.f + expf(-u));
}

// ---------------- launcher with fork/join overlap ---------------------------
extern "C" void kernel_launch(void* const* d_in, const int* in_sizes, int n_in,
                              void* d_out, int out_size) {
    const float* x   = (const float*)d_in[0];
    const int*   ei  = (const int*)d_in[1];
    const float* W1  = (const float*)d_in[2];
    const float* b1  = (const float*)d_in[3];
    const float* W2  = (const float*)d_in[4];
    const float* b2  = (const float*)d_in[5];
    const float* Wfc = (const float*)d_in[6];
    const float* bfc = (const float*)d_in[7];
    float* out = (float*)d_out;

    const int* row = ei;            // sources
    const int* col = ei + N_EDGES;  // targets

    static cudaStream_t side = nullptr;
    static cudaEvent_t  evFork = nullptr, evJoin = nullptr;
    if (side == nullptr) {
        cudaStreamCreateWithFlags(&side, cudaStreamNonBlocking);
        cudaEventCreateWithFlags(&evFork, cudaEventDisableTiming);
        cudaEventCreateWithFlags(&evJoin, cudaEventDisableTiming);
    }

    void* counts_ptr = nullptr;
    cudaGetSymbolAddress(&counts_ptr, d_counts);

    // fork: side stream does weight prep + GEMM (independent of edges)
    cudaEventRecord(evFork, 0);
    cudaStreamWaitEvent(side, evFork, 0);
    prep_weights_kernel<<<33, 256, 0, side>>>(W1, W2, b2, Wfc, bfc);
    gemm1_mma_kernel<<<GEMM_BLOCKS, 256, 0, side>>>(x);

    // main stream: counts reset + ELL build
    cudaMemsetAsync(counts_ptr, 0, N_NODES * sizeof(int), 0);
    fill_ell_kernel<<<(N_EDGES / 4 + 255) / 256, 256, 0, 0>>>(row, col);

    // join
    cudaEventRecord(evJoin, side);
    cudaStreamWaitEvent(0, evJoin, 0);

    scale_g_kernel<<<(SCALE_HALF + 255) / 256, 256, 0, 0>>>();
    agg1_kernel<<<(N_NODES + 7) / 8, 256, 0, 0>>>(b1);
    agg2_kernel<<<(N_NODES + 255) / 256, 256, 0, 0>>>(out);
}